// round 11
// baseline (speedup 1.0000x reference)
#include <cuda_runtime.h>
#include <math.h>

#define BB   32
#define TT   8192
#define SS   32
#define IND  128
#define HH   256
#define NTOK (BB*TT)
#define TPB  64                 // tokens per MLP block
#define NMLP (NTOK/TPB)         // 4096
#define NCHUNK (TT/TPB)         // 128 chunks per batch
#define NSCAN 16                // scan blocks (2 batches each)

// output section offsets (floats): emissions, state_probs, ll, trans, best_path, path_score
#define PROBS_OFF  8388608L
#define LL_OFF     16777216L
#define TRANS_OFF  16777248L
#define BP_OFF     16778272L
#define PS_OFF     17040416L

__device__ unsigned char g_bp[(size_t)NTOK * SS];
__device__ float g_trans[SS * SS];
__device__ float g_logtrans[SS * SS];
__device__ float g_loginit[SS];
__device__ int   g_last[BB];
__device__ int   g_flag[BB * NCHUNK];

__device__ __forceinline__ float gelu_exact(float v) {
    return 0.5f * v * (1.0f + erff(v * 0.70710678118654752440f));
}
__device__ __forceinline__ float wmax(float v) {
    #pragma unroll
    for (int o = 16; o; o >>= 1) v = fmaxf(v, __shfl_xor_sync(~0u, v, o));
    return v;
}
__device__ __forceinline__ float wsum(float v) {
    #pragma unroll
    for (int o = 16; o; o >>= 1) v += __shfl_xor_sync(~0u, v, o);
    return v;
}
__device__ __forceinline__ unsigned long long pk2(float lo, float hi) {
    unsigned long long r;
    asm("mov.b64 %0, {%1, %2};" : "=l"(r) : "f"(lo), "f"(hi));
    return r;
}
__device__ __forceinline__ void fma2(unsigned long long& acc, unsigned long long a,
                                     unsigned long long b) {
    asm("fma.rn.f32x2 %0, %1, %2, %0;" : "+l"(acc) : "l"(a), "l"(b));
}
__device__ __forceinline__ void upk2(unsigned long long v, float& lo, float& hi) {
    asm("mov.b64 {%0, %1}, %2;" : "=f"(lo), "=f"(hi) : "l"(v));
}

// ---------------- kernel 0: params + flag reset ----------------
__global__ void __launch_bounds__(1024) k_params(const float* __restrict__ il,
                                                 const float* __restrict__ tl,
                                                 float* __restrict__ trans_out)
{
    const int w = threadIdx.x >> 5, lane = threadIdx.x & 31;
    for (int i = threadIdx.x; i < BB * NCHUNK; i += 1024) g_flag[i] = 0;
    {
        float vv = tl[w * SS + lane];
        float m = wmax(vv);
        float e = expf(vv - m);
        float s = wsum(e);
        float tr = e / s;
        g_trans[w * SS + lane] = tr;
        trans_out[w * SS + lane] = tr;
        g_logtrans[w * SS + lane] = logf(tr + 1e-10f);
    }
    if (w == 0) {
        float vv = il[lane];
        float m = wmax(vv);
        float e = expf(vv - m);
        float s = wsum(e);
        g_loginit[lane] = logf(e / s + 1e-10f);
    }
}

// ---------------- fused kernel ----------------
// smem floats (28672 = 114688 B = 14 x 8KB pages -> 2 blocks/SM):
//   SH1 @0      [64][256] (16384)  -- SH2 overlays after stage B (post-sync)
//   WB  @16384  [16][256] (4096)   -- weight k-chunk
//   SX  @20480  [64][128] (8192)   -- dead after stage A;
//                                     MUS overlays @20480 (post-stage-A),
//                                     W3B overlays @20480 in stage C (MUS dead)
#define SM_FLOATS 28672
#define MLP_SMEM_BYTES (SM_FLOATS * 4)

__global__ void __launch_bounds__(256, 2) k_fused(
    const float* __restrict__ x,
    const float* __restrict__ W1, const float* __restrict__ b1,
    const float* __restrict__ lng, const float* __restrict__ lnb,
    const float* __restrict__ W2, const float* __restrict__ b2,
    const float* __restrict__ W3, const float* __restrict__ b3,
    float* emis, float* probs, float* ll, float* ps)
{
    // ================= scan blocks (persistent consumers) =================
    if (blockIdx.x < NSCAN) {
        const int wid = threadIdx.x >> 5, j = threadIdx.x & 31;
        if (wid >= 4) return;
        const int b = 2 * (int)blockIdx.x + (wid >> 1);
        const float* em = emis + (size_t)b * TT * SS;

        if ((wid & 1) == 0) {
            // forward scan (lagged-max rescaled) + fused state_probs
            float* pr = probs + (size_t)b * TT * SS;
            float tr[32];
            #pragma unroll
            for (int i = 0; i < 32; i++) tr[i] = g_trans[i * SS + j] + 1e-10f;

            float a = 0.f, m = 0.f, mnext = 0.f;
            for (int c = 0; c < NCHUNK; c++) {
                while (__ldcg(&g_flag[c * BB + b]) == 0) __nanosleep(64);
                __threadfence();
                int t0 = TPB * c;
                const int t1 = t0 + TPB - 1;
                if (c == 0) {
                    a = g_loginit[j] + __ldcg(em + j);
                    m = wmax(a);
                    mnext = m;
                    float e0 = __expf(a - m);
                    float s0 = wsum(e0);
                    pr[j] = __fdividef(e0, s0);
                    t0 = 1;
                }
                float emA = __ldcg(em + (size_t)t0 * SS + j);
                float emB = __ldcg(em + (size_t)((t0 + 1 <= t1) ? t0 + 1 : t1) * SS + j);
                for (int t = t0; t <= t1; t++) {
                    float emv = emA; emA = emB;
                    int tn = (t + 2 <= t1) ? t + 2 : t1;
                    emB = __ldcg(em + (size_t)tn * SS + j);

                    float e = __expf(a - m);
                    float s0 = 0.f, s1 = 0.f, s2 = 0.f, s3 = 0.f;
                    #pragma unroll
                    for (int i = 0; i < 32; i += 4) {
                        s0 = fmaf(__shfl_sync(~0u, e, i    ), tr[i    ], s0);
                        s1 = fmaf(__shfl_sync(~0u, e, i + 1), tr[i + 1], s1);
                        s2 = fmaf(__shfl_sync(~0u, e, i + 2), tr[i + 2], s2);
                        s3 = fmaf(__shfl_sync(~0u, e, i + 3), tr[i + 3], s3);
                    }
                    a = emv + m + __logf((s0 + s1) + (s2 + s3));
                    m = mnext;
                    mnext = wmax(a);
                    float e2 = __expf(a - mnext);
                    float ss = wsum(e2);
                    pr[(size_t)t * SS + j] = __fdividef(e2, ss);
                }
            }
            float e = __expf(a - mnext);
            float sum = wsum(e);
            if (j == 0) ll[b] = mnext + __logf(sum);
        } else {
            // Viterbi scan
            unsigned char* bprow = g_bp + (size_t)b * TT * SS;
            float lt[32];
            #pragma unroll
            for (int i = 0; i < 32; i++) lt[i] = g_logtrans[i * SS + j];

            float v = 0.f;
            for (int c = 0; c < NCHUNK; c++) {
                while (__ldcg(&g_flag[c * BB + b]) == 0) __nanosleep(64);
                __threadfence();
                int t0 = TPB * c;
                const int t1 = t0 + TPB - 1;
                if (c == 0) {
                    v = g_loginit[j] + __ldcg(em + j);
                    t0 = 1;
                }
                float emA = __ldcg(em + (size_t)t0 * SS + j);
                float emB = __ldcg(em + (size_t)((t0 + 1 <= t1) ? t0 + 1 : t1) * SS + j);
                for (int t = t0; t <= t1; t++) {
                    float emv = emA; emA = emB;
                    int tn = (t + 2 <= t1) ? t + 2 : t1;
                    emB = __ldcg(em + (size_t)tn * SS + j);

                    float bv[4]; int bi[4];
                    #pragma unroll
                    for (int cc = 0; cc < 4; cc++) {
                        const int base = cc * 8;
                        float best = __shfl_sync(~0u, v, base) + lt[base];
                        int idx = base;
                        #pragma unroll
                        for (int q = 1; q < 8; q++) {
                            float cand = __shfl_sync(~0u, v, base + q) + lt[base + q];
                            if (cand > best) { best = cand; idx = base + q; }
                        }
                        bv[cc] = best; bi[cc] = idx;
                    }
                    float best = bv[0]; int idx = bi[0];
                    #pragma unroll
                    for (int cc = 1; cc < 4; cc++)
                        if (bv[cc] > best) { best = bv[cc]; idx = bi[cc]; }
                    v = best + emv;
                    bprow[(size_t)t * SS + j] = (unsigned char)idx;
                }
            }
            float bvv = v; int bj = j;
            #pragma unroll
            for (int o = 16; o; o >>= 1) {
                float ov = __shfl_xor_sync(~0u, bvv, o);
                int   oi = __shfl_xor_sync(~0u, bj, o);
                if (ov > bvv || (ov == bvv && oi < bj)) { bvv = ov; bj = oi; }
            }
            if (j == 0) { ps[b] = bvv; g_last[b] = bj; }
        }
        return;
    }

    // ================= MLP blocks (producer), 64 tokens, time-major =================
    extern __shared__ float sm[];
    float* SH1 = sm;              // SH2 overlays post-stage-B
    float* SH2 = sm;
    float* WB  = sm + 16384;      // 4096 floats (16 rows x 256)
    float* SX  = sm + 20480;      // 8192 floats
    float* MUS = sm + 20480;      // overlays SX (written post-stage-A)
    float* W3B = sm + 20480;      // overlays SX/MUS in stage C

    const int tid = threadIdx.x;
    const int w = tid >> 5, lane = tid & 31;
    const int imlp = blockIdx.x - NSCAN;       // 0..4095
    const int cchunk = imlp >> 5;              // 0..127
    const int bb = imlp & 31;
    const size_t tok0 = (size_t)bb * TT + (size_t)TPB * cchunk;

    {   // load x tile: 64 tokens x 128 = 8192 floats
        const float4* xg = (const float4*)(x + tok0 * IND);
        float4* d = (float4*)SX;
        #pragma unroll
        for (int i = 0; i < 8; i++) d[tid + 256 * i] = xg[tid + 256 * i];
    }

    // accumulators: 8 tokens x 4 column-pairs (cols j0 = 2*lane + 64*u)
    unsigned long long acc2[8][4];
    #pragma unroll
    for (int t = 0; t < 8; t++)
        #pragma unroll
        for (int u = 0; u < 4; u++) acc2[t][u] = 0ull;

    // ---- stage A: h1 = x @ W1 (16-row weight chunks, direct gmem->smem) ----
    for (int kc = 0; kc < IND; kc += 16) {
        __syncthreads();
        {   // natural-layout weight chunk [16][256]
            const float4* wg = (const float4*)(W1 + (size_t)kc * HH);
            float4* d = (float4*)WB;
            d[tid]       = wg[tid];
            d[tid + 256] = wg[tid + 256];
            d[tid + 512] = wg[tid + 512];
            d[tid + 768] = wg[tid + 768];
        }
        __syncthreads();
        #pragma unroll
        for (int k = 0; k < 16; k++) {
            unsigned long long xp[8];
            #pragma unroll
            for (int t = 0; t < 8; t++) {
                float xs = SX[(8 * w + t) * IND + kc + k];   // broadcast
                xp[t] = pk2(xs, xs);
            }
            #pragma unroll
            for (int u = 0; u < 4; u++) {
                unsigned long long wv2 =
                    *(const unsigned long long*)&WB[k * HH + 2 * lane + 64 * u];
                #pragma unroll
                for (int t = 0; t < 8; t++) fma2(acc2[t][u], xp[t], wv2);
            }
        }
    }
    __syncthreads();    // SX reads complete -> SX region free (MUS may be written)
    #pragma unroll
    for (int u = 0; u < 4; u++) {
        int j0 = 2 * lane + 64 * u;
        float2 bb2 = *(const float2*)&b1[j0];
        #pragma unroll
        for (int t = 0; t < 8; t++) {
            float lo, hi;
            upk2(acc2[t][u], lo, hi);
            *(float2*)&SH1[(8 * w + t) * HH + j0] = make_float2(lo + bb2.x, hi + bb2.y);
        }
    }
    __syncthreads();

    // ---- LayerNorm stats (warp w: tokens 8w..8w+7) ----
    #pragma unroll
    for (int i = 0; i < 8; i++) {
        int t = 8 * w + i;
        float s = 0.f, ss = 0.f;
        #pragma unroll
        for (int u = 0; u < 8; u++) {
            float v = SH1[t * HH + lane + 32 * u];
            s += v; ss = fmaf(v, v, ss);
        }
        s = wsum(s); ss = wsum(ss);
        if (lane == 0) {
            float mu = s * (1.f / HH);
            float var = ss * (1.f / HH) - mu * mu;
            MUS[2 * t] = mu;
            MUS[2 * t + 1] = rsqrtf(var + 1e-5f);
        }
    }
    __syncthreads();

    // ---- LN transform + GELU in place ----
    {
        float gv = lng[tid], bv = lnb[tid];
        #pragma unroll 8
        for (int t = 0; t < TPB; t++) {
            float v = SH1[t * HH + tid];
            v = (v - MUS[2 * t]) * MUS[2 * t + 1] * gv + bv;
            SH1[t * HH + tid] = gelu_exact(v);
        }
    }

    // ---- stage B: h2 = gelu(g1 @ W2 + b2) ----
    #pragma unroll
    for (int t = 0; t < 8; t++)
        #pragma unroll
        for (int u = 0; u < 4; u++) acc2[t][u] = 0ull;

    for (int kc = 0; kc < HH; kc += 16) {
        __syncthreads();
        {
            const float4* wg = (const float4*)(W2 + (size_t)kc * HH);
            float4* d = (float4*)WB;
            d[tid]       = wg[tid];
            d[tid + 256] = wg[tid + 256];
            d[tid + 512] = wg[tid + 512];
            d[tid + 768] = wg[tid + 768];
        }
        __syncthreads();
        #pragma unroll
        for (int k = 0; k < 16; k++) {
            unsigned long long xp[8];
            #pragma unroll
            for (int t = 0; t < 8; t++) {
                float xs = SH1[(8 * w + t) * HH + kc + k];   // broadcast
                xp[t] = pk2(xs, xs);
            }
            #pragma unroll
            for (int u = 0; u < 4; u++) {
                unsigned long long wv2 =
                    *(const unsigned long long*)&WB[k * HH + 2 * lane + 64 * u];
                #pragma unroll
                for (int t = 0; t < 8; t++) fma2(acc2[t][u], xp[t], wv2);
            }
        }
    }
    __syncthreads();   // all SH1 reads complete -> safe to overlay with SH2
    #pragma unroll
    for (int u = 0; u < 4; u++) {
        int j0 = 2 * lane + 64 * u;
        float2 bb2 = *(const float2*)&b2[j0];
        #pragma unroll
        for (int t = 0; t < 8; t++) {
            float lo, hi;
            upk2(acc2[t][u], lo, hi);
            *(float2*)&SH2[(8 * w + t) * HH + j0] =
                make_float2(gelu_exact(lo + bb2.x), gelu_exact(hi + bb2.y));
        }
    }
    __syncthreads();   // WB/SX/MUS dead -> W3B region valid

    // ---- stage C: logits = h2 @ W3 + b3 -> log_softmax ----
    {
        const float4* wg = (const float4*)W3;
        float4* d = (float4*)W3B;
        #pragma unroll
        for (int i = 0; i < 8; i++) d[tid + 256 * i] = wg[tid + 256 * i];
    }
    __syncthreads();

    // token pairs p: (8w+2p, 8w+2p+1); lane = output state
    unsigned long long acc3[4] = {0ull, 0ull, 0ull, 0ull};
    for (int k4 = 0; k4 < HH / 4; k4++) {
        float4 xa[8];
        #pragma unroll
        for (int t = 0; t < 8; t++)
            xa[t] = *(const float4*)&SH2[(8 * w + t) * HH + 4 * k4];   // broadcast
        #pragma unroll
        for (int q = 0; q < 4; q++) {
            float wv = W3B[(4 * k4 + q) * SS + lane];
            unsigned long long wv2 = pk2(wv, wv);
            #pragma unroll
            for (int p = 0; p < 4; p++) {
                float x0 = q == 0 ? xa[2 * p].x : q == 1 ? xa[2 * p].y : q == 2 ? xa[2 * p].z : xa[2 * p].w;
                float x1 = q == 0 ? xa[2 * p + 1].x : q == 1 ? xa[2 * p + 1].y : q == 2 ? xa[2 * p + 1].z : xa[2 * p + 1].w;
                fma2(acc3[p], pk2(x0, x1), wv2);
            }
        }
    }
    float bbv = b3[lane];
    #pragma unroll
    for (int p = 0; p < 4; p++) {
        float v0, v1;
        upk2(acc3[p], v0, v1);
        #pragma unroll
        for (int h = 0; h < 2; h++) {
            float v = (h == 0 ? v0 : v1) + bbv;
            float m = wmax(v);
            float e = expf(v - m);
            float s = wsum(e);
            emis[(tok0 + 8 * w + 2 * p + h) * SS + lane] = v - m - logf(s);
        }
    }

    // ---- publish chunk ----
    __threadfence();
    __syncthreads();
    if (tid == 0) atomicExch(&g_flag[imlp], 1);
}

// ---------------- backtrace: segment composition ----------------
__global__ void __launch_bounds__(1024) k_backtrace(float* __restrict__ bp_out)
{
    __shared__ int comp[32][32];
    __shared__ int entry_s[32];
    const int b = blockIdx.x;
    const int seg = threadIdx.x >> 5, e = threadIdx.x & 31;
    const unsigned char* bp = g_bp + (size_t)b * TT * SS;
    const int tTop = seg * 256 + 255;

    int st = e;
    for (int t = tTop; t >= seg * 256 + 1; t--)
        st = bp[(size_t)t * SS + st];
    comp[seg][e] = st;
    __syncthreads();

    if (threadIdx.x == 0) {
        int cur = g_last[b];
        for (int s = 31; s >= 0; s--) {
            entry_s[s] = cur;
            int ex = comp[s][cur];
            if (s > 0) cur = bp[(size_t)(256 * s) * SS + ex];
        }
    }
    __syncthreads();

    if (e == 0) {
        int cur = entry_s[seg];
        float* o = bp_out + (size_t)b * TT;
        o[tTop] = (float)cur;
        for (int t = tTop; t >= seg * 256 + 1; t--) {
            cur = bp[(size_t)t * SS + cur];
            o[t - 1] = (float)cur;
        }
    }
}

extern "C" void kernel_launch(void* const* d_in, const int* in_sizes, int n_in,
                              void* d_out, int out_size)
{
    const float* x   = (const float*)d_in[0];
    const float* il  = (const float*)d_in[1];
    const float* tl  = (const float*)d_in[2];
    const float* W1  = (const float*)d_in[3];
    const float* b1  = (const float*)d_in[4];
    const float* lng = (const float*)d_in[5];
    const float* lnb = (const float*)d_in[6];
    const float* W2  = (const float*)d_in[7];
    const float* b2  = (const float*)d_in[8];
    const float* W3  = (const float*)d_in[9];
    const float* b3  = (const float*)d_in[10];
    float* out = (float*)d_out;

    static bool attr_done = false;
    if (!attr_done) {
        cudaFuncSetAttribute(k_fused, cudaFuncAttributeMaxDynamicSharedMemorySize, MLP_SMEM_BYTES);
        attr_done = true;
    }

    k_params<<<1, 1024>>>(il, tl, out + TRANS_OFF);
    k_fused<<<NSCAN + NMLP, 256, MLP_SMEM_BYTES>>>(x, W1, b1, lng, lnb, W2, b2, W3, b3,
                                                   out, out + PROBS_OFF,
                                                   out + LL_OFF, out + PS_OFF);
    k_backtrace<<<BB, 1024>>>(out + BP_OFF);
}

// round 12
// speedup vs baseline: 1.1245x; 1.1245x over previous
#include <cuda_runtime.h>
#include <math.h>

#define BB   32
#define TT   8192
#define SS   32
#define IND  128
#define HH   256
#define NTOK (BB*TT)
#define TPB  64                 // tokens per MLP block
#define NMLP (NTOK/TPB)         // 4096
#define NCHUNK (TT/TPB)         // 128 chunks per batch
#define NSCAN 16                // scan blocks (2 batches each)

// output section offsets (floats): emissions, state_probs, ll, trans, best_path, path_score
#define PROBS_OFF  8388608L
#define LL_OFF     16777216L
#define TRANS_OFF  16777248L
#define BP_OFF     16778272L
#define PS_OFF     17040416L

__device__ unsigned char g_bp[(size_t)NTOK * SS];
__device__ float g_trans[SS * SS];
__device__ float g_logtrans[SS * SS];
__device__ float g_loginit[SS];
__device__ int   g_last[BB];
__device__ int   g_flag[BB * NCHUNK];

__device__ __forceinline__ float gelu_exact(float v) {
    return 0.5f * v * (1.0f + erff(v * 0.70710678118654752440f));
}
__device__ __forceinline__ float wmax(float v) {
    #pragma unroll
    for (int o = 16; o; o >>= 1) v = fmaxf(v, __shfl_xor_sync(~0u, v, o));
    return v;
}
__device__ __forceinline__ float wsum(float v) {
    #pragma unroll
    for (int o = 16; o; o >>= 1) v += __shfl_xor_sync(~0u, v, o);
    return v;
}
__device__ __forceinline__ unsigned long long pk2(float lo, float hi) {
    unsigned long long r;
    asm("mov.b64 %0, {%1, %2};" : "=l"(r) : "f"(lo), "f"(hi));
    return r;
}
__device__ __forceinline__ void fma2(unsigned long long& acc, unsigned long long a,
                                     unsigned long long b) {
    asm("fma.rn.f32x2 %0, %1, %2, %0;" : "+l"(acc) : "l"(a), "l"(b));
}
__device__ __forceinline__ void upk2(unsigned long long v, float& lo, float& hi) {
    asm("mov.b64 {%0, %1}, %2;" : "=f"(lo), "=f"(hi) : "l"(v));
}

// ---------------- kernel 0: params + flag reset ----------------
__global__ void __launch_bounds__(1024) k_params(const float* __restrict__ il,
                                                 const float* __restrict__ tl,
                                                 float* __restrict__ trans_out)
{
    const int w = threadIdx.x >> 5, lane = threadIdx.x & 31;
    for (int i = threadIdx.x; i < BB * NCHUNK; i += 1024) g_flag[i] = 0;
    {
        float vv = tl[w * SS + lane];
        float m = wmax(vv);
        float e = expf(vv - m);
        float s = wsum(e);
        float tr = e / s;
        g_trans[w * SS + lane] = tr;
        trans_out[w * SS + lane] = tr;
        g_logtrans[w * SS + lane] = logf(tr + 1e-10f);
    }
    if (w == 0) {
        float vv = il[lane];
        float m = wmax(vv);
        float e = expf(vv - m);
        float s = wsum(e);
        g_loginit[lane] = logf(e / s + 1e-10f);
    }
}

// dummy launch to shift the ncu profile window onto k_fused (4th launch)
__global__ void k_nop() {}

// ---------------- fused kernel ----------------
// smem floats (49280 = 192.5 KB -> 1 block/SM, same occupancy as champion):
//   SH1 @0      [64][256] (16384)
//   SH2 @16384  [64][256] (16384)
//   WB0 @32768  [16][256] (4096)
//   SX  @36864  [64][128] (8192)   -- stage C reuses as W3B [256][32]
//   MUS @45056  [128]
//   WB1 @45184  [16][256] (4096)
#define SM_FLOATS 49280
#define MLP_SMEM_BYTES (SM_FLOATS * 4)

__global__ void __launch_bounds__(256) k_fused(
    const float* __restrict__ x,
    const float* __restrict__ W1, const float* __restrict__ b1,
    const float* __restrict__ lng, const float* __restrict__ lnb,
    const float* __restrict__ W2, const float* __restrict__ b2,
    const float* __restrict__ W3, const float* __restrict__ b3,
    float* emis, float* probs, float* ll, float* ps)
{
    // ================= scan blocks (persistent consumers) =================
    if (blockIdx.x < NSCAN) {
        const int wid = threadIdx.x >> 5, j = threadIdx.x & 31;
        if (wid >= 4) return;
        const int b = 2 * (int)blockIdx.x + (wid >> 1);
        const float* em = emis + (size_t)b * TT * SS;

        if ((wid & 1) == 0) {
            // forward scan (lagged-max rescaled) + fused state_probs
            float* pr = probs + (size_t)b * TT * SS;
            float tr[32];
            #pragma unroll
            for (int i = 0; i < 32; i++) tr[i] = g_trans[i * SS + j] + 1e-10f;

            float a = 0.f, m = 0.f, mnext = 0.f;
            for (int c = 0; c < NCHUNK; c++) {
                while (__ldcg(&g_flag[c * BB + b]) == 0) __nanosleep(64);
                __threadfence();
                int t0 = TPB * c;
                const int t1 = t0 + TPB - 1;
                if (c == 0) {
                    a = g_loginit[j] + __ldcg(em + j);
                    m = wmax(a);
                    mnext = m;
                    float e0 = __expf(a - m);
                    float s0 = wsum(e0);
                    pr[j] = __fdividef(e0, s0);
                    t0 = 1;
                }
                float emA = __ldcg(em + (size_t)t0 * SS + j);
                float emB = __ldcg(em + (size_t)((t0 + 1 <= t1) ? t0 + 1 : t1) * SS + j);
                for (int t = t0; t <= t1; t++) {
                    float emv = emA; emA = emB;
                    int tn = (t + 2 <= t1) ? t + 2 : t1;
                    emB = __ldcg(em + (size_t)tn * SS + j);

                    float e = __expf(a - m);
                    float s0 = 0.f, s1 = 0.f, s2 = 0.f, s3 = 0.f;
                    #pragma unroll
                    for (int i = 0; i < 32; i += 4) {
                        s0 = fmaf(__shfl_sync(~0u, e, i    ), tr[i    ], s0);
                        s1 = fmaf(__shfl_sync(~0u, e, i + 1), tr[i + 1], s1);
                        s2 = fmaf(__shfl_sync(~0u, e, i + 2), tr[i + 2], s2);
                        s3 = fmaf(__shfl_sync(~0u, e, i + 3), tr[i + 3], s3);
                    }
                    a = emv + m + __logf((s0 + s1) + (s2 + s3));
                    m = mnext;
                    mnext = wmax(a);
                    float e2 = __expf(a - mnext);
                    float ss = wsum(e2);
                    pr[(size_t)t * SS + j] = __fdividef(e2, ss);
                }
            }
            float e = __expf(a - mnext);
            float sum = wsum(e);
            if (j == 0) ll[b] = mnext + __logf(sum);
        } else {
            // Viterbi scan
            unsigned char* bprow = g_bp + (size_t)b * TT * SS;
            float lt[32];
            #pragma unroll
            for (int i = 0; i < 32; i++) lt[i] = g_logtrans[i * SS + j];

            float v = 0.f;
            for (int c = 0; c < NCHUNK; c++) {
                while (__ldcg(&g_flag[c * BB + b]) == 0) __nanosleep(64);
                __threadfence();
                int t0 = TPB * c;
                const int t1 = t0 + TPB - 1;
                if (c == 0) {
                    v = g_loginit[j] + __ldcg(em + j);
                    t0 = 1;
                }
                float emA = __ldcg(em + (size_t)t0 * SS + j);
                float emB = __ldcg(em + (size_t)((t0 + 1 <= t1) ? t0 + 1 : t1) * SS + j);
                for (int t = t0; t <= t1; t++) {
                    float emv = emA; emA = emB;
                    int tn = (t + 2 <= t1) ? t + 2 : t1;
                    emB = __ldcg(em + (size_t)tn * SS + j);

                    float bv[4]; int bi[4];
                    #pragma unroll
                    for (int cc = 0; cc < 4; cc++) {
                        const int base = cc * 8;
                        float best = __shfl_sync(~0u, v, base) + lt[base];
                        int idx = base;
                        #pragma unroll
                        for (int q = 1; q < 8; q++) {
                            float cand = __shfl_sync(~0u, v, base + q) + lt[base + q];
                            if (cand > best) { best = cand; idx = base + q; }
                        }
                        bv[cc] = best; bi[cc] = idx;
                    }
                    float best = bv[0]; int idx = bi[0];
                    #pragma unroll
                    for (int cc = 1; cc < 4; cc++)
                        if (bv[cc] > best) { best = bv[cc]; idx = bi[cc]; }
                    v = best + emv;
                    bprow[(size_t)t * SS + j] = (unsigned char)idx;
                }
            }
            float bvv = v; int bj = j;
            #pragma unroll
            for (int o = 16; o; o >>= 1) {
                float ov = __shfl_xor_sync(~0u, bvv, o);
                int   oi = __shfl_xor_sync(~0u, bj, o);
                if (ov > bvv || (ov == bvv && oi < bj)) { bvv = ov; bj = oi; }
            }
            if (j == 0) { ps[b] = bvv; g_last[b] = bj; }
        }
        return;
    }

    // ================= MLP blocks (producer), 64 tokens, time-major =================
    extern __shared__ float sm[];
    float* SH1 = sm;
    float* SH2 = sm + 16384;
    float* WB0 = sm + 32768;
    float* SX  = sm + 36864;
    float* W3B = sm + 36864;      // overlays SX (dead after stage A)
    float* MUS = sm + 45056;
    float* WB1 = sm + 45184;

    const int tid = threadIdx.x;
    const int w = tid >> 5, lane = tid & 31;
    const int imlp = blockIdx.x - NSCAN;       // 0..4095
    const int cchunk = imlp >> 5;              // 0..127
    const int bb = imlp & 31;
    const size_t tok0 = (size_t)bb * TT + (size_t)TPB * cchunk;

    {   // load x tile: 64 tokens x 128 = 8192 floats
        const float4* xg = (const float4*)(x + tok0 * IND);
        float4* d = (float4*)SX;
        #pragma unroll
        for (int i = 0; i < 8; i++) d[tid + 256 * i] = xg[tid + 256 * i];
    }

    // accumulators: 8 tokens x 4 column-pairs (cols j0 = 2*lane + 64*u)
    unsigned long long acc2[8][4];
    #pragma unroll
    for (int t = 0; t < 8; t++)
        #pragma unroll
        for (int u = 0; u < 4; u++) acc2[t][u] = 0ull;

    // ---- stage A: h1 = x @ W1  (ping-pong WB, 1 sync/chunk) ----
    float4 pf0, pf1, pf2, pf3;
    {
        const float4* wg = (const float4*)W1;
        pf0 = wg[tid]; pf1 = wg[tid + 256]; pf2 = wg[tid + 512]; pf3 = wg[tid + 768];
        float4* d = (float4*)WB0;
        d[tid] = pf0; d[tid + 256] = pf1; d[tid + 512] = pf2; d[tid + 768] = pf3;
    }
    __syncthreads();   // WB0 ready AND x tile ready

    #pragma unroll
    for (int cc = 0; cc < IND / 16; cc++) {               // 8 chunks
        float* cur = (cc & 1) ? WB1 : WB0;
        float* nxt = (cc & 1) ? WB0 : WB1;
        const int kc = cc * 16;
        if (cc + 1 < IND / 16) {                          // prefetch next chunk (LDG hides under compute)
            const float4* wg = (const float4*)(W1 + (size_t)(kc + 16) * HH);
            pf0 = wg[tid]; pf1 = wg[tid + 256]; pf2 = wg[tid + 512]; pf3 = wg[tid + 768];
        }
        #pragma unroll
        for (int k = 0; k < 16; k++) {
            unsigned long long xp[8];
            #pragma unroll
            for (int t = 0; t < 8; t++) {
                float xs = SX[(8 * w + t) * IND + kc + k];   // broadcast
                xp[t] = pk2(xs, xs);
            }
            #pragma unroll
            for (int u = 0; u < 4; u++) {
                unsigned long long wv2 =
                    *(const unsigned long long*)&cur[k * HH + 2 * lane + 64 * u];
                #pragma unroll
                for (int t = 0; t < 8; t++) fma2(acc2[t][u], xp[t], wv2);
            }
        }
        if (cc + 1 < IND / 16) {
            float4* d = (float4*)nxt;
            d[tid] = pf0; d[tid + 256] = pf1; d[tid + 512] = pf2; d[tid + 768] = pf3;
            __syncthreads();
        }
    }
    __syncthreads();
    #pragma unroll
    for (int u = 0; u < 4; u++) {
        int j0 = 2 * lane + 64 * u;
        float2 bb2 = *(const float2*)&b1[j0];
        #pragma unroll
        for (int t = 0; t < 8; t++) {
            float lo, hi;
            upk2(acc2[t][u], lo, hi);
            *(float2*)&SH1[(8 * w + t) * HH + j0] = make_float2(lo + bb2.x, hi + bb2.y);
        }
    }
    __syncthreads();

    // ---- LayerNorm stats (warp w: tokens 8w..8w+7) ----
    #pragma unroll
    for (int i = 0; i < 8; i++) {
        int t = 8 * w + i;
        float s = 0.f, ss = 0.f;
        #pragma unroll
        for (int u = 0; u < 8; u++) {
            float v = SH1[t * HH + lane + 32 * u];
            s += v; ss = fmaf(v, v, ss);
        }
        s = wsum(s); ss = wsum(ss);
        if (lane == 0) {
            float mu = s * (1.f / HH);
            float var = ss * (1.f / HH) - mu * mu;
            MUS[2 * t] = mu;
            MUS[2 * t + 1] = rsqrtf(var + 1e-5f);
        }
    }
    __syncthreads();

    // ---- LN transform + GELU in place ----
    {
        float gv = lng[tid], bv = lnb[tid];
        #pragma unroll 8
        for (int t = 0; t < TPB; t++) {
            float v = SH1[t * HH + tid];
            v = (v - MUS[2 * t]) * MUS[2 * t + 1] * gv + bv;
            SH1[t * HH + tid] = gelu_exact(v);
        }
    }

    // ---- stage B: h2 = gelu(g1 @ W2 + b2)  (ping-pong WB, 1 sync/chunk) ----
    #pragma unroll
    for (int t = 0; t < 8; t++)
        #pragma unroll
        for (int u = 0; u < 4; u++) acc2[t][u] = 0ull;

    {
        const float4* wg = (const float4*)W2;
        pf0 = wg[tid]; pf1 = wg[tid + 256]; pf2 = wg[tid + 512]; pf3 = wg[tid + 768];
        float4* d = (float4*)WB0;
        d[tid] = pf0; d[tid + 256] = pf1; d[tid + 512] = pf2; d[tid + 768] = pf3;
    }
    __syncthreads();   // WB0 ready AND SH1 (post-GELU) ready

    #pragma unroll
    for (int cc = 0; cc < HH / 16; cc++) {                // 16 chunks
        float* cur = (cc & 1) ? WB1 : WB0;
        float* nxt = (cc & 1) ? WB0 : WB1;
        const int kc = cc * 16;
        if (cc + 1 < HH / 16) {
            const float4* wg = (const float4*)(W2 + (size_t)(kc + 16) * HH);
            pf0 = wg[tid]; pf1 = wg[tid + 256]; pf2 = wg[tid + 512]; pf3 = wg[tid + 768];
        }
        #pragma unroll
        for (int k = 0; k < 16; k++) {
            unsigned long long xp[8];
            #pragma unroll
            for (int t = 0; t < 8; t++) {
                float xs = SH1[(8 * w + t) * HH + kc + k];   // broadcast
                xp[t] = pk2(xs, xs);
            }
            #pragma unroll
            for (int u = 0; u < 4; u++) {
                unsigned long long wv2 =
                    *(const unsigned long long*)&cur[k * HH + 2 * lane + 64 * u];
                #pragma unroll
                for (int t = 0; t < 8; t++) fma2(acc2[t][u], xp[t], wv2);
            }
        }
        if (cc + 1 < HH / 16) {
            float4* d = (float4*)nxt;
            d[tid] = pf0; d[tid + 256] = pf1; d[tid + 512] = pf2; d[tid + 768] = pf3;
            __syncthreads();
        }
    }
    __syncthreads();
    #pragma unroll
    for (int u = 0; u < 4; u++) {
        int j0 = 2 * lane + 64 * u;
        float2 bb2 = *(const float2*)&b2[j0];
        #pragma unroll
        for (int t = 0; t < 8; t++) {
            float lo, hi;
            upk2(acc2[t][u], lo, hi);
            *(float2*)&SH2[(8 * w + t) * HH + j0] =
                make_float2(gelu_exact(lo + bb2.x), gelu_exact(hi + bb2.y));
        }
    }
    __syncthreads();   // SX dead -> W3B region valid

    // ---- stage C: logits = h2 @ W3 + b3 -> log_softmax ----
    {
        const float4* wg = (const float4*)W3;
        float4* d = (float4*)W3B;
        #pragma unroll
        for (int i = 0; i < 8; i++) d[tid + 256 * i] = wg[tid + 256 * i];
    }
    __syncthreads();

    // token pairs p: (8w+2p, 8w+2p+1); lane = output state
    unsigned long long acc3[4] = {0ull, 0ull, 0ull, 0ull};
    for (int k4 = 0; k4 < HH / 4; k4++) {
        float4 xa[8];
        #pragma unroll
        for (int t = 0; t < 8; t++)
            xa[t] = *(const float4*)&SH2[(8 * w + t) * HH + 4 * k4];   // broadcast
        #pragma unroll
        for (int q = 0; q < 4; q++) {
            float wv = W3B[(4 * k4 + q) * SS + lane];
            unsigned long long wv2 = pk2(wv, wv);
            #pragma unroll
            for (int p = 0; p < 4; p++) {
                float x0 = q == 0 ? xa[2 * p].x : q == 1 ? xa[2 * p].y : q == 2 ? xa[2 * p].z : xa[2 * p].w;
                float x1 = q == 0 ? xa[2 * p + 1].x : q == 1 ? xa[2 * p + 1].y : q == 2 ? xa[2 * p + 1].z : xa[2 * p + 1].w;
                fma2(acc3[p], pk2(x0, x1), wv2);
            }
        }
    }
    float bbv = b3[lane];
    #pragma unroll
    for (int p = 0; p < 4; p++) {
        float v0, v1;
        upk2(acc3[p], v0, v1);
        #pragma unroll
        for (int h = 0; h < 2; h++) {
            float v = (h == 0 ? v0 : v1) + bbv;
            float m = wmax(v);
            float e = expf(v - m);
            float s = wsum(e);
            emis[(tok0 + 8 * w + 2 * p + h) * SS + lane] = v - m - logf(s);
        }
    }

    // ---- publish chunk ----
    __threadfence();
    __syncthreads();
    if (tid == 0) atomicExch(&g_flag[imlp], 1);
}

// ---------------- backtrace: segment composition ----------------
__global__ void __launch_bounds__(1024) k_backtrace(float* __restrict__ bp_out)
{
    __shared__ int comp[32][32];
    __shared__ int entry_s[32];
    const int b = blockIdx.x;
    const int seg = threadIdx.x >> 5, e = threadIdx.x & 31;
    const unsigned char* bp = g_bp + (size_t)b * TT * SS;
    const int tTop = seg * 256 + 255;

    int st = e;
    for (int t = tTop; t >= seg * 256 + 1; t--)
        st = bp[(size_t)t * SS + st];
    comp[seg][e] = st;
    __syncthreads();

    if (threadIdx.x == 0) {
        int cur = g_last[b];
        for (int s = 31; s >= 0; s--) {
            entry_s[s] = cur;
            int ex = comp[s][cur];
            if (s > 0) cur = bp[(size_t)(256 * s) * SS + ex];
        }
    }
    __syncthreads();

    if (e == 0) {
        int cur = entry_s[seg];
        float* o = bp_out + (size_t)b * TT;
        o[tTop] = (float)cur;
        for (int t = tTop; t >= seg * 256 + 1; t--) {
            cur = bp[(size_t)t * SS + cur];
            o[t - 1] = (float)cur;
        }
    }
}

extern "C" void kernel_launch(void* const* d_in, const int* in_sizes, int n_in,
                              void* d_out, int out_size)
{
    const float* x   = (const float*)d_in[0];
    const float* il  = (const float*)d_in[1];
    const float* tl  = (const float*)d_in[2];
    const float* W1  = (const float*)d_in[3];
    const float* b1  = (const float*)d_in[4];
    const float* lng = (const float*)d_in[5];
    const float* lnb = (const float*)d_in[6];
    const float* W2  = (const float*)d_in[7];
    const float* b2  = (const float*)d_in[8];
    const float* W3  = (const float*)d_in[9];
    const float* b3  = (const float*)d_in[10];
    float* out = (float*)d_out;

    static bool attr_done = false;
    if (!attr_done) {
        cudaFuncSetAttribute(k_fused, cudaFuncAttributeMaxDynamicSharedMemorySize, MLP_SMEM_BYTES);
        attr_done = true;
    }

    k_params<<<1, 1024>>>(il, tl, out + TRANS_OFF);
    k_nop<<<1, 32>>>();     // shift ncu window: 4th launch = k_fused
    k_nop<<<1, 32>>>();
    k_fused<<<NSCAN + NMLP, 256, MLP_SMEM_BYTES>>>(x, W1, b1, lng, lnb, W2, b2, W3, b3,
                                                   out, out + PROBS_OFF,
                                                   out + LL_OFF, out + PS_OFF);
    k_backtrace<<<BB, 1024>>>(out + BP_OFF);
}

// round 13
// speedup vs baseline: 1.1268x; 1.0020x over previous
#include <cuda_runtime.h>
#include <math.h>

#define BB   32
#define TT   8192
#define SS   32
#define IND  128
#define HH   256
#define NTOK (BB*TT)
#define TPB  64                 // tokens per MLP block
#define NMLP (NTOK/TPB)         // 4096
#define NCHUNK (TT/TPB)         // 128 chunks per batch
#define NSCAN 16                // scan blocks (2 batches each)
#define DST  130                // duplicated-tile row stride (words), odd*2 to spread banks

// output section offsets (floats): emissions, state_probs, ll, trans, best_path, path_score
#define PROBS_OFF  8388608L
#define LL_OFF     16777216L
#define TRANS_OFF  16777248L
#define BP_OFF     16778272L
#define PS_OFF     17040416L

__device__ unsigned char g_bp[(size_t)NTOK * SS];
__device__ float g_trans[SS * SS];
__device__ float g_logtrans[SS * SS];
__device__ float g_loginit[SS];
__device__ int   g_last[BB];
__device__ int   g_flag[BB * NCHUNK];

__device__ __forceinline__ float gelu_exact(float v) {
    return 0.5f * v * (1.0f + erff(v * 0.70710678118654752440f));
}
__device__ __forceinline__ float wmax(float v) {
    #pragma unroll
    for (int o = 16; o; o >>= 1) v = fmaxf(v, __shfl_xor_sync(~0u, v, o));
    return v;
}
__device__ __forceinline__ float wsum(float v) {
    #pragma unroll
    for (int o = 16; o; o >>= 1) v += __shfl_xor_sync(~0u, v, o);
    return v;
}
__device__ __forceinline__ unsigned long long pk2(float lo, float hi) {
    unsigned long long r;
    asm("mov.b64 %0, {%1, %2};" : "=l"(r) : "f"(lo), "f"(hi));
    return r;
}
__device__ __forceinline__ void fma2(unsigned long long& acc, unsigned long long a,
                                     unsigned long long b) {
    asm("fma.rn.f32x2 %0, %1, %2, %0;" : "+l"(acc) : "l"(a), "l"(b));
}
__device__ __forceinline__ void upk2(unsigned long long v, float& lo, float& hi) {
    asm("mov.b64 {%0, %1}, %2;" : "=f"(lo), "=f"(hi) : "l"(v));
}

// ---------------- kernel 0: params + flag reset ----------------
__global__ void __launch_bounds__(1024) k_params(const float* __restrict__ il,
                                                 const float* __restrict__ tl,
                                                 float* __restrict__ trans_out)
{
    const int w = threadIdx.x >> 5, lane = threadIdx.x & 31;
    for (int i = threadIdx.x; i < BB * NCHUNK; i += 1024) g_flag[i] = 0;
    {
        float vv = tl[w * SS + lane];
        float m = wmax(vv);
        float e = expf(vv - m);
        float s = wsum(e);
        float tr = e / s;
        g_trans[w * SS + lane] = tr;
        trans_out[w * SS + lane] = tr;
        g_logtrans[w * SS + lane] = logf(tr + 1e-10f);
    }
    if (w == 0) {
        float vv = il[lane];
        float m = wmax(vv);
        float e = expf(vv - m);
        float s = wsum(e);
        g_loginit[lane] = logf(e / s + 1e-10f);
    }
}

// dummy launch to shift the ncu profile window onto k_fused (4th launch)
__global__ void k_nop() {}

// ---------------- fused kernel ----------------
// smem floats (41344 = 161.5 KB -> 1 block/SM, 8 warps, same occ as champion):
//   DUP @0      [128][130] (16640)  duplicated (v,v) k-major tile:
//                                   stage A: x-dup; stage B: h1-dup (per 128-col half)
//                                   stage C: W3B overlays [0,8192)
//   SH1 @16640  [64][256]  (16384)  -- SH2 overlays after stage B
//   WB0 @33024  [16][256]  (4096)
//   WB1 @37120  [16][256]  (4096)
//   MUS @41216  [128]
#define SM_FLOATS 41344
#define MLP_SMEM_BYTES (SM_FLOATS * 4)

__global__ void __launch_bounds__(256) k_fused(
    const float* __restrict__ x,
    const float* __restrict__ W1, const float* __restrict__ b1,
    const float* __restrict__ lng, const float* __restrict__ lnb,
    const float* __restrict__ W2, const float* __restrict__ b2,
    const float* __restrict__ W3, const float* __restrict__ b3,
    float* emis, float* probs, float* ll, float* ps)
{
    // ================= scan blocks (persistent consumers) =================
    if (blockIdx.x < NSCAN) {
        const int wid = threadIdx.x >> 5, j = threadIdx.x & 31;
        if (wid >= 4) return;
        const int b = 2 * (int)blockIdx.x + (wid >> 1);
        const float* em = emis + (size_t)b * TT * SS;

        if ((wid & 1) == 0) {
            // forward scan (lagged-max rescaled) + fused state_probs
            float* pr = probs + (size_t)b * TT * SS;
            float tr[32];
            #pragma unroll
            for (int i = 0; i < 32; i++) tr[i] = g_trans[i * SS + j] + 1e-10f;

            float a = 0.f, m = 0.f, mnext = 0.f;
            for (int c = 0; c < NCHUNK; c++) {
                while (__ldcg(&g_flag[c * BB + b]) == 0) __nanosleep(64);
                __threadfence();
                int t0 = TPB * c;
                const int t1 = t0 + TPB - 1;
                if (c == 0) {
                    a = g_loginit[j] + __ldcg(em + j);
                    m = wmax(a);
                    mnext = m;
                    float e0 = __expf(a - m);
                    float s0 = wsum(e0);
                    pr[j] = __fdividef(e0, s0);
                    t0 = 1;
                }
                float emA = __ldcg(em + (size_t)t0 * SS + j);
                float emB = __ldcg(em + (size_t)((t0 + 1 <= t1) ? t0 + 1 : t1) * SS + j);
                for (int t = t0; t <= t1; t++) {
                    float emv = emA; emA = emB;
                    int tn = (t + 2 <= t1) ? t + 2 : t1;
                    emB = __ldcg(em + (size_t)tn * SS + j);

                    float e = __expf(a - m);
                    float s0 = 0.f, s1 = 0.f, s2 = 0.f, s3 = 0.f;
                    #pragma unroll
                    for (int i = 0; i < 32; i += 4) {
                        s0 = fmaf(__shfl_sync(~0u, e, i    ), tr[i    ], s0);
                        s1 = fmaf(__shfl_sync(~0u, e, i + 1), tr[i + 1], s1);
                        s2 = fmaf(__shfl_sync(~0u, e, i + 2), tr[i + 2], s2);
                        s3 = fmaf(__shfl_sync(~0u, e, i + 3), tr[i + 3], s3);
                    }
                    a = emv + m + __logf((s0 + s1) + (s2 + s3));
                    m = mnext;
                    mnext = wmax(a);
                    float e2 = __expf(a - mnext);
                    float ss = wsum(e2);
                    pr[(size_t)t * SS + j] = __fdividef(e2, ss);
                }
            }
            float e = __expf(a - mnext);
            float sum = wsum(e);
            if (j == 0) ll[b] = mnext + __logf(sum);
        } else {
            // Viterbi scan
            unsigned char* bprow = g_bp + (size_t)b * TT * SS;
            float lt[32];
            #pragma unroll
            for (int i = 0; i < 32; i++) lt[i] = g_logtrans[i * SS + j];

            float v = 0.f;
            for (int c = 0; c < NCHUNK; c++) {
                while (__ldcg(&g_flag[c * BB + b]) == 0) __nanosleep(64);
                __threadfence();
                int t0 = TPB * c;
                const int t1 = t0 + TPB - 1;
                if (c == 0) {
                    v = g_loginit[j] + __ldcg(em + j);
                    t0 = 1;
                }
                float emA = __ldcg(em + (size_t)t0 * SS + j);
                float emB = __ldcg(em + (size_t)((t0 + 1 <= t1) ? t0 + 1 : t1) * SS + j);
                for (int t = t0; t <= t1; t++) {
                    float emv = emA; emA = emB;
                    int tn = (t + 2 <= t1) ? t + 2 : t1;
                    emB = __ldcg(em + (size_t)tn * SS + j);

                    float bv[4]; int bi[4];
                    #pragma unroll
                    for (int cc = 0; cc < 4; cc++) {
                        const int base = cc * 8;
                        float best = __shfl_sync(~0u, v, base) + lt[base];
                        int idx = base;
                        #pragma unroll
                        for (int q = 1; q < 8; q++) {
                            float cand = __shfl_sync(~0u, v, base + q) + lt[base + q];
                            if (cand > best) { best = cand; idx = base + q; }
                        }
                        bv[cc] = best; bi[cc] = idx;
                    }
                    float best = bv[0]; int idx = bi[0];
                    #pragma unroll
                    for (int cc = 1; cc < 4; cc++)
                        if (bv[cc] > best) { best = bv[cc]; idx = bi[cc]; }
                    v = best + emv;
                    bprow[(size_t)t * SS + j] = (unsigned char)idx;
                }
            }
            float bvv = v; int bj = j;
            #pragma unroll
            for (int o = 16; o; o >>= 1) {
                float ov = __shfl_xor_sync(~0u, bvv, o);
                int   oi = __shfl_xor_sync(~0u, bj, o);
                if (ov > bvv || (ov == bvv && oi < bj)) { bvv = ov; bj = oi; }
            }
            if (j == 0) { ps[b] = bvv; g_last[b] = bj; }
        }
        return;
    }

    // ================= MLP blocks (producer), 64 tokens, time-major =================
    extern __shared__ float sm[];
    float* DUP = sm;              // [128][DST] duplicated pairs, k-major
    float* SH1 = sm + 16640;      // SH2 overlays post-stage-B
    float* SH2 = sm + 16640;
    float* WB0 = sm + 33024;
    float* WB1 = sm + 37120;
    float* MUS = sm + 41216;
    float* W3B = sm;              // stage C overlays DUP

    const int tid = threadIdx.x;
    const int w = tid >> 5, lane = tid & 31;
    const int imlp = blockIdx.x - NSCAN;       // 0..4095
    const int cchunk = imlp >> 5;              // 0..127
    const int bb = imlp & 31;
    const size_t tok0 = (size_t)bb * TT + (size_t)TPB * cchunk;

    {   // load x tile, writing DUPLICATED k-major pairs: DUP[k][2*tok] = (v,v)
        const float4* xg = (const float4*)(x + tok0 * IND);
        #pragma unroll
        for (int i = 0; i < 8; i++) {
            float4 v = xg[tid + 256 * i];
            int f = tid + 256 * i;
            int tok = f >> 5;             // 0..63 (w + 8i)
            int k0 = (f & 31) * 4;        // 4*lane
            float* base = DUP + (size_t)k0 * DST + 2 * tok;
            *(float2*)(base)           = make_float2(v.x, v.x);
            *(float2*)(base + DST)     = make_float2(v.y, v.y);
            *(float2*)(base + 2 * DST) = make_float2(v.z, v.z);
            *(float2*)(base + 3 * DST) = make_float2(v.w, v.w);
        }
    }

    // accumulators: 8 tokens x 4 column-pairs (cols j0 = 2*lane + 64*u)
    unsigned long long acc2[8][4];
    #pragma unroll
    for (int t = 0; t < 8; t++)
        #pragma unroll
        for (int u = 0; u < 4; u++) acc2[t][u] = 0ull;

    // ---- stage A: h1 = x @ W1  (ping-pong WB, duplicated x via LDS.64) ----
    float4 pf0, pf1, pf2, pf3;
    {
        const float4* wg = (const float4*)W1;
        pf0 = wg[tid]; pf1 = wg[tid + 256]; pf2 = wg[tid + 512]; pf3 = wg[tid + 768];
        float4* d = (float4*)WB0;
        d[tid] = pf0; d[tid + 256] = pf1; d[tid + 512] = pf2; d[tid + 768] = pf3;
    }
    __syncthreads();   // WB0 + DUP(x) ready

    #pragma unroll
    for (int cc = 0; cc < IND / 16; cc++) {               // 8 chunks
        float* cur = (cc & 1) ? WB1 : WB0;
        float* nxt = (cc & 1) ? WB0 : WB1;
        const int kc = cc * 16;
        if (cc + 1 < IND / 16) {
            const float4* wg = (const float4*)(W1 + (size_t)(kc + 16) * HH);
            pf0 = wg[tid]; pf1 = wg[tid + 256]; pf2 = wg[tid + 512]; pf3 = wg[tid + 768];
        }
        #pragma unroll
        for (int k = 0; k < 16; k++) {
            const float* xrow = DUP + (size_t)(kc + k) * DST + 16 * w;
            unsigned long long xp[8];
            #pragma unroll
            for (int t = 0; t < 8; t++)
                xp[t] = *(const unsigned long long*)(xrow + 2 * t);   // (v,v) broadcast
            #pragma unroll
            for (int u = 0; u < 4; u++) {
                unsigned long long wv2 =
                    *(const unsigned long long*)&cur[k * HH + 2 * lane + 64 * u];
                #pragma unroll
                for (int t = 0; t < 8; t++) fma2(acc2[t][u], xp[t], wv2);
            }
        }
        if (cc + 1 < IND / 16) {
            float4* d = (float4*)nxt;
            d[tid] = pf0; d[tid + 256] = pf1; d[tid + 512] = pf2; d[tid + 768] = pf3;
            __syncthreads();
        }
    }
    __syncthreads();
    #pragma unroll
    for (int u = 0; u < 4; u++) {
        int j0 = 2 * lane + 64 * u;
        float2 bb2 = *(const float2*)&b1[j0];
        #pragma unroll
        for (int t = 0; t < 8; t++) {
            float lo, hi;
            upk2(acc2[t][u], lo, hi);
            *(float2*)&SH1[(8 * w + t) * HH + j0] = make_float2(lo + bb2.x, hi + bb2.y);
        }
    }
    __syncthreads();

    // ---- LayerNorm stats (warp w: tokens 8w..8w+7) ----
    #pragma unroll
    for (int i = 0; i < 8; i++) {
        int t = 8 * w + i;
        float s = 0.f, ss = 0.f;
        #pragma unroll
        for (int u = 0; u < 8; u++) {
            float v = SH1[t * HH + lane + 32 * u];
            s += v; ss = fmaf(v, v, ss);
        }
        s = wsum(s); ss = wsum(ss);
        if (lane == 0) {
            float mu = s * (1.f / HH);
            float var = ss * (1.f / HH) - mu * mu;
            MUS[2 * t] = mu;
            MUS[2 * t + 1] = rsqrtf(var + 1e-5f);
        }
    }
    __syncthreads();

    // ---- LN transform + GELU in place (SH1 <- gelu(LN(SH1))) ----
    {
        float gv = lng[tid], bv = lnb[tid];
        #pragma unroll 8
        for (int t = 0; t < TPB; t++) {
            float v = SH1[t * HH + tid];
            v = (v - MUS[2 * t]) * MUS[2 * t + 1] * gv + bv;
            SH1[t * HH + tid] = gelu_exact(v);
        }
    }

    // ---- stage B: h2 = gelu(g1 @ W2 + b2), two 128-col k-halves ----
    #pragma unroll
    for (int t = 0; t < 8; t++)
        #pragma unroll
        for (int u = 0; u < 4; u++) acc2[t][u] = 0ull;

    #pragma unroll
    for (int h = 0; h < 2; h++) {
        // duplication pass: DUP[kl][2t] = (g1[t][128h+kl], same), kl in [0,128)
        __syncthreads();   // SH1 ready (h=0) / previous half's DUP reads done (h=1)
        {
            int c = tid & 127;                 // local k col
            int tb = (tid >> 7) * 32;          // token range start
            #pragma unroll 8
            for (int t = tb; t < tb + 32; t++) {
                float v = SH1[t * HH + 128 * h + c];
                *(float2*)&DUP[(size_t)c * DST + 2 * t] = make_float2(v, v);
            }
        }
        // first weight chunk of this half into WB0 + prefetch next
        {
            const float4* wg = (const float4*)(W2 + (size_t)(128 * h) * HH);
            pf0 = wg[tid]; pf1 = wg[tid + 256]; pf2 = wg[tid + 512]; pf3 = wg[tid + 768];
            float4* d = (float4*)WB0;
            d[tid] = pf0; d[tid + 256] = pf1; d[tid + 512] = pf2; d[tid + 768] = pf3;
        }
        __syncthreads();   // DUP + WB0 ready

        #pragma unroll
        for (int cc = 0; cc < 8; cc++) {                  // 8 chunks of 16 k
            float* cur = (cc & 1) ? WB1 : WB0;
            float* nxt = (cc & 1) ? WB0 : WB1;
            const int kc = cc * 16;                        // local k within half
            if (cc + 1 < 8) {
                const float4* wg = (const float4*)(W2 + (size_t)(128 * h + kc + 16) * HH);
                pf0 = wg[tid]; pf1 = wg[tid + 256]; pf2 = wg[tid + 512]; pf3 = wg[tid + 768];
            }
            #pragma unroll
            for (int k = 0; k < 16; k++) {
                const float* xrow = DUP + (size_t)(kc + k) * DST + 16 * w;
                unsigned long long xp[8];
                #pragma unroll
                for (int t = 0; t < 8; t++)
                    xp[t] = *(const unsigned long long*)(xrow + 2 * t);
                #pragma unroll
                for (int u = 0; u < 4; u++) {
                    unsigned long long wv2 =
                        *(const unsigned long long*)&cur[k * HH + 2 * lane + 64 * u];
                    #pragma unroll
                    for (int t = 0; t < 8; t++) fma2(acc2[t][u], xp[t], wv2);
                }
            }
            if (cc + 1 < 8) {
                float4* d = (float4*)nxt;
                d[tid] = pf0; d[tid + 256] = pf1; d[tid + 512] = pf2; d[tid + 768] = pf3;
                __syncthreads();
            }
        }
    }
    __syncthreads();   // all SH1/DUP reads done -> SH2 overlay + DUP reuse legal
    #pragma unroll
    for (int u = 0; u < 4; u++) {
        int j0 = 2 * lane + 64 * u;
        float2 bb2 = *(const float2*)&b2[j0];
        #pragma unroll
        for (int t = 0; t < 8; t++) {
            float lo, hi;
            upk2(acc2[t][u], lo, hi);
            *(float2*)&SH2[(8 * w + t) * HH + j0] =
                make_float2(gelu_exact(lo + bb2.x), gelu_exact(hi + bb2.y));
        }
    }
    __syncthreads();   // DUP dead -> W3B region valid

    // ---- stage C: logits = h2 @ W3 + b3 -> log_softmax ----
    {
        const float4* wg = (const float4*)W3;
        float4* d = (float4*)W3B;
        #pragma unroll
        for (int i = 0; i < 8; i++) d[tid + 256 * i] = wg[tid + 256 * i];
    }
    __syncthreads();

    // token pairs p: (8w+2p, 8w+2p+1); lane = output state
    unsigned long long acc3[4] = {0ull, 0ull, 0ull, 0ull};
    for (int k4 = 0; k4 < HH / 4; k4++) {
        float4 xa[8];
        #pragma unroll
        for (int t = 0; t < 8; t++)
            xa[t] = *(const float4*)&SH2[(8 * w + t) * HH + 4 * k4];   // broadcast
        #pragma unroll
        for (int q = 0; q < 4; q++) {
            float wv = W3B[(4 * k4 + q) * SS + lane];
            unsigned long long wv2 = pk2(wv, wv);
            #pragma unroll
            for (int p = 0; p < 4; p++) {
                float x0 = q == 0 ? xa[2 * p].x : q == 1 ? xa[2 * p].y : q == 2 ? xa[2 * p].z : xa[2 * p].w;
                float x1 = q == 0 ? xa[2 * p + 1].x : q == 1 ? xa[2 * p + 1].y : q == 2 ? xa[2 * p + 1].z : xa[2 * p + 1].w;
                fma2(acc3[p], pk2(x0, x1), wv2);
            }
        }
    }
    float bbv = b3[lane];
    #pragma unroll
    for (int p = 0; p < 4; p++) {
        float v0, v1;
        upk2(acc3[p], v0, v1);
        #pragma unroll
        for (int h = 0; h < 2; h++) {
            float v = (h == 0 ? v0 : v1) + bbv;
            float m = wmax(v);
            float e = expf(v - m);
            float s = wsum(e);
            emis[(tok0 + 8 * w + 2 * p + h) * SS + lane] = v - m - logf(s);
        }
    }

    // ---- publish chunk ----
    __threadfence();
    __syncthreads();
    if (tid == 0) atomicExch(&g_flag[imlp], 1);
}

// ---------------- backtrace: segment composition ----------------
__global__ void __launch_bounds__(1024) k_backtrace(float* __restrict__ bp_out)
{
    __shared__ int comp[32][32];
    __shared__ int entry_s[32];
    const int b = blockIdx.x;
    const int seg = threadIdx.x >> 5, e = threadIdx.x & 31;
    const unsigned char* bp = g_bp + (size_t)b * TT * SS;
    const int tTop = seg * 256 + 255;

    int st = e;
    for (int t = tTop; t >= seg * 256 + 1; t--)
        st = bp[(size_t)t * SS + st];
    comp[seg][e] = st;
    __syncthreads();

    if (threadIdx.x == 0) {
        int cur = g_last[b];
        for (int s = 31; s >= 0; s--) {
            entry_s[s] = cur;
            int ex = comp[s][cur];
            if (s > 0) cur = bp[(size_t)(256 * s) * SS + ex];
        }
    }
    __syncthreads();

    if (e == 0) {
        int cur = entry_s[seg];
        float* o = bp_out + (size_t)b * TT;
        o[tTop] = (float)cur;
        for (int t = tTop; t >= seg * 256 + 1; t--) {
            cur = bp[(size_t)t * SS + cur];
            o[t - 1] = (float)cur;
        }
    }
}

extern "C" void kernel_launch(void* const* d_in, const int* in_sizes, int n_in,
                              void* d_out, int out_size)
{
    const float* x   = (const float*)d_in[0];
    const float* il  = (const float*)d_in[1];
    const float* tl  = (const float*)d_in[2];
    const float* W1  = (const float*)d_in[3];
    const float* b1  = (const float*)d_in[4];
    const float* lng = (const float*)d_in[5];
    const float* lnb = (const float*)d_in[6];
    const float* W2  = (const float*)d_in[7];
    const float* b2  = (const float*)d_in[8];
    const float* W3  = (const float*)d_in[9];
    const float* b3  = (const float*)d_in[10];
    float* out = (float*)d_out;

    static bool attr_done = false;
    if (!attr_done) {
        cudaFuncSetAttribute(k_fused, cudaFuncAttributeMaxDynamicSharedMemorySize, MLP_SMEM_BYTES);
        attr_done = true;
    }

    k_params<<<1, 1024>>>(il, tl, out + TRANS_OFF);
    k_nop<<<1, 32>>>();     // keep ncu window on k_fused (4th launch)
    k_nop<<<1, 32>>>();
    k_fused<<<NSCAN + NMLP, 256, MLP_SMEM_BYTES>>>(x, W1, b1, lng, lnb, W2, b2, W3, b3,
                                                   out, out + PROBS_OFF,
                                                   out + LL_OFF, out + PS_OFF);
    k_backtrace<<<BB, 1024>>>(out + BP_OFF);
}